// round 2
// baseline (speedup 1.0000x reference)
#include <cuda_runtime.h>

#define NP 10000
#define NR 4096
#define NCHUNK 20
#define PPC 500     // points per chunk (NCHUNK * PPC == NP)
#define TILE 64

// ---- static scratch (no allocations allowed) ----
__device__ float4 g_pt[NP];          // pos.xyz, delta
__device__ float  g_sf[NP];          // sigma * opacity
__device__ float4 g_ro[NR];          // ray origin
__device__ float4 g_dn[NR];          // normalized dir
__device__ float  g_sh[NR * 16];     // SH basis per ray
__device__ float  g_part[5 * NCHUNK * NR];
__device__ float  g_opmean;

__device__ __forceinline__ float finv(float x) { return __fdividef(1.0f, x); }
__device__ __forceinline__ float fsigmoid(float x) { return __fdividef(1.0f, 1.0f + __expf(-x)); }

__global__ void prep_points(const float* __restrict__ positions,
                            const int*   __restrict__ sidx,
                            const float* __restrict__ log_delta,
                            const float* __restrict__ log_sigma,
                            const float* __restrict__ raw_op) {
    int i = blockIdx.x * blockDim.x + threadIdx.x;
    if (i >= NP) return;
    int s = sidx[i];
    float delta = __expf(log_delta[s]);
    float sigma = __expf(log_sigma[s]);
    float op    = fsigmoid(raw_op[i]);
    g_pt[i] = make_float4(positions[i*3+0], positions[i*3+1], positions[i*3+2], delta);
    g_sf[i] = sigma * op;
}

__global__ void op_mean_k(const float* __restrict__ raw_op) {
    __shared__ float red[256];
    float s = 0.0f;
    for (int i = threadIdx.x; i < NP; i += 256) s += fsigmoid(raw_op[i]);
    red[threadIdx.x] = s;
    __syncthreads();
    for (int o = 128; o > 0; o >>= 1) {
        if (threadIdx.x < o) red[threadIdx.x] += red[threadIdx.x + o];
        __syncthreads();
    }
    if (threadIdx.x == 0) g_opmean = red[0] * (1.0f / (float)NP);
}

__global__ void prep_rays(const float* __restrict__ rays_o,
                          const float* __restrict__ rays_d) {
    int i = blockIdx.x * blockDim.x + threadIdx.x;
    if (i >= NR) return;
    float ox = rays_o[i*3+0], oy = rays_o[i*3+1], oz = rays_o[i*3+2];
    float dx = rays_d[i*3+0], dy = rays_d[i*3+1], dz = rays_d[i*3+2];
    float inv = rsqrtf(dx*dx + dy*dy + dz*dz);
    float x = dx * inv, y = dy * inv, z = dz * inv;
    g_ro[i] = make_float4(ox, oy, oz, 0.0f);
    g_dn[i] = make_float4(x, y, z, 0.0f);
    float* sh = &g_sh[i * 16];
    sh[0]  = 0.282095f;
    sh[1]  = 0.488603f * y;
    sh[2]  = 0.488603f * z;
    sh[3]  = 0.488603f * x;
    sh[4]  = 1.092548f * x * y;
    sh[5]  = 1.092548f * y * z;
    sh[6]  = 0.315392f * (3.0f * z * z - 1.0f);
    sh[7]  = 1.092548f * x * z;
    sh[8]  = 0.546274f * (x * x - y * y);
    sh[9]  = 0.590044f * y * (3.0f * x * x - y * y);
    sh[10] = 2.890611f * x * y * z;
    sh[11] = 0.457046f * y * (5.0f * z * z - 1.0f);
    sh[12] = 0.373176f * z * (5.0f * z * z - 3.0f);
    sh[13] = 0.457046f * x * (5.0f * z * z - 1.0f);
    sh[14] = 1.445306f * z * (x * x - y * y);
    sh[15] = 0.590044f * x * (x * x - 3.0f * y * y);
}

__global__ void __launch_bounds__(256, 2)
main_k(const float* __restrict__ sh_coeffs) {
    int ray   = blockIdx.x * 256 + threadIdx.x;
    int chunk = blockIdx.y;

    float4 o4 = g_ro[ray];
    float4 d4 = g_dn[ray];
    float sh[16];
#pragma unroll
    for (int k = 0; k < 16; k++) sh[k] = g_sh[ray * 16 + k];

    float S = 0.0f, ar = 0.0f, ag = 0.0f, ab = 0.0f, ad = 0.0f;

    __shared__ float4 s_pt[TILE];
    __shared__ float  s_sf[TILE];
    __shared__ float  s_cf[TILE * 48];

    int p0 = chunk * PPC;
    for (int base = p0; base < p0 + PPC; base += TILE) {
        int cnt = min(TILE, p0 + PPC - base);
        __syncthreads();
        for (int i = threadIdx.x; i < cnt; i += 256) {
            s_pt[i] = g_pt[base + i];
            s_sf[i] = g_sf[base + i];
        }
        // 48 contiguous floats per point -> coalesced float4 copies
        const float4* src = (const float4*)(sh_coeffs + (size_t)base * 48);
        float4* dst = (float4*)s_cf;
        for (int i = threadIdx.x; i < cnt * 12; i += 256) dst[i] = src[i];
        __syncthreads();

        for (int j = 0; j < cnt; j++) {
            float4 p = s_pt[j];
            float rx = p.x - o4.x, ry = p.y - o4.y, rz = p.z - o4.z;
            float d2   = rx*rx + ry*ry + rz*rz;
            float rinv = rsqrtf(d2);
            float dist = d2 * rinv;
            float rdot = rx*d4.x + ry*d4.y + rz*d4.z;
            float dot  = rdot * finv(dist + 1e-8f);
            float t    = 1.0f - dot;
            float w    = __expf(-p.w * t * t) * s_sf[j] * finv(dist + 1e-6f);

            const float* cf = &s_cf[j * 48];
            float l0a = 0, l0b = 0, l1a = 0, l1b = 0, l2a = 0, l2b = 0;
#pragma unroll
            for (int k = 0; k < 16; k += 2) {
                l0a += cf[k*3 + 0] * sh[k];
                l1a += cf[k*3 + 1] * sh[k];
                l2a += cf[k*3 + 2] * sh[k];
                l0b += cf[k*3 + 3] * sh[k + 1];
                l1b += cf[k*3 + 4] * sh[k + 1];
                l2b += cf[k*3 + 5] * sh[k + 1];
            }
            float c0 = fsigmoid(l0a + l0b);
            float c1 = fsigmoid(l1a + l1b);
            float c2 = fsigmoid(l2a + l2b);

            S  += w;
            ad += w * dist;
            ar += w * c0;
            ag += w * c1;
            ab += w * c2;
        }
    }

    int idx = chunk * NR + ray;
    g_part[0 * NCHUNK * NR + idx] = S;
    g_part[1 * NCHUNK * NR + idx] = ar;
    g_part[2 * NCHUNK * NR + idx] = ag;
    g_part[3 * NCHUNK * NR + idx] = ab;
    g_part[4 * NCHUNK * NR + idx] = ad;
}

__global__ void finalize(float* __restrict__ out) {
    int ray = blockIdx.x * 256 + threadIdx.x;
    if (ray >= NR) return;
    float S = 0, ar = 0, ag = 0, ab = 0, ad = 0;
#pragma unroll
    for (int c = 0; c < NCHUNK; c++) {
        int idx = c * NR + ray;
        S  += g_part[0 * NCHUNK * NR + idx];
        ar += g_part[1 * NCHUNK * NR + idx];
        ag += g_part[2 * NCHUNK * NR + idx];
        ab += g_part[3 * NCHUNK * NR + idx];
        ad += g_part[4 * NCHUNK * NR + idx];
    }
    float inv = __fdividef(1.0f, S + 1e-8f);
    out[ray*3 + 0] = ar * inv;
    out[ray*3 + 1] = ag * inv;
    out[ray*3 + 2] = ab * inv;
    out[3*NR + ray] = ad * inv;   // depth
    out[4*NR + ray] = g_opmean;   // opac (broadcast mean opacity)
}

extern "C" void kernel_launch(void* const* d_in, const int* in_sizes, int n_in,
                              void* d_out, int out_size) {
    const float* rays_o    = (const float*)d_in[0];
    const float* rays_d    = (const float*)d_in[1];
    const float* positions = (const float*)d_in[2];
    const int*   sidx      = (const int*)  d_in[3];
    const float* log_delta = (const float*)d_in[4];
    const float* log_sigma = (const float*)d_in[5];
    const float* raw_op    = (const float*)d_in[6];
    const float* shc       = (const float*)d_in[7];
    float* out = (float*)d_out;

    prep_points<<<(NP + 255) / 256, 256>>>(positions, sidx, log_delta, log_sigma, raw_op);
    op_mean_k<<<1, 256>>>(raw_op);
    prep_rays<<<NR / 256, 256>>>(rays_o, rays_d);
    main_k<<<dim3(16, NCHUNK), 256>>>(shc);
    finalize<<<NR / 256, 256>>>(out);
}

// round 3
// speedup vs baseline: 1.2031x; 1.2031x over previous
#include <cuda_runtime.h>

#define NP 10000
#define NR 4096
#define NCHUNK 20
#define PPC 500     // points per chunk (NCHUNK * PPC == NP)
#define TILE 64

// ---- static scratch (no allocations allowed) ----
__device__ float4 g_pt[NP];          // pos.xyz, delta
__device__ float  g_sf[NP];          // sigma * opacity
__device__ float4 g_ro[NR];          // ray origin
__device__ float4 g_dn[NR];          // normalized dir
__device__ float  g_sh[NR * 16];     // SH basis per ray
__device__ float  g_part[5 * NCHUNK * NR];
__device__ float  g_opmean;

__device__ __forceinline__ float fsigmoid(float x) { return __fdividef(1.0f, 1.0f + __expf(-x)); }

__global__ void prep_points(const float* __restrict__ positions,
                            const int*   __restrict__ sidx,
                            const float* __restrict__ log_delta,
                            const float* __restrict__ log_sigma,
                            const float* __restrict__ raw_op) {
    int i = blockIdx.x * blockDim.x + threadIdx.x;
    if (i >= NP) return;
    int s = sidx[i];
    float delta = __expf(log_delta[s]);
    float sigma = __expf(log_sigma[s]);
    float op    = fsigmoid(raw_op[i]);
    g_pt[i] = make_float4(positions[i*3+0], positions[i*3+1], positions[i*3+2], delta);
    g_sf[i] = sigma * op;
}

__global__ void op_mean_k(const float* __restrict__ raw_op) {
    __shared__ float red[256];
    float s = 0.0f;
    for (int i = threadIdx.x; i < NP; i += 256) s += fsigmoid(raw_op[i]);
    red[threadIdx.x] = s;
    __syncthreads();
    for (int o = 128; o > 0; o >>= 1) {
        if (threadIdx.x < o) red[threadIdx.x] += red[threadIdx.x + o];
        __syncthreads();
    }
    if (threadIdx.x == 0) g_opmean = red[0] * (1.0f / (float)NP);
}

__global__ void prep_rays(const float* __restrict__ rays_o,
                          const float* __restrict__ rays_d) {
    int i = blockIdx.x * blockDim.x + threadIdx.x;
    if (i >= NR) return;
    float ox = rays_o[i*3+0], oy = rays_o[i*3+1], oz = rays_o[i*3+2];
    float dx = rays_d[i*3+0], dy = rays_d[i*3+1], dz = rays_d[i*3+2];
    float inv = rsqrtf(dx*dx + dy*dy + dz*dz);
    float x = dx * inv, y = dy * inv, z = dz * inv;
    g_ro[i] = make_float4(ox, oy, oz, 0.0f);
    g_dn[i] = make_float4(x, y, z, 0.0f);
    float* sh = &g_sh[i * 16];
    sh[0]  = 0.282095f;
    sh[1]  = 0.488603f * y;
    sh[2]  = 0.488603f * z;
    sh[3]  = 0.488603f * x;
    sh[4]  = 1.092548f * x * y;
    sh[5]  = 1.092548f * y * z;
    sh[6]  = 0.315392f * (3.0f * z * z - 1.0f);
    sh[7]  = 1.092548f * x * z;
    sh[8]  = 0.546274f * (x * x - y * y);
    sh[9]  = 0.590044f * y * (3.0f * x * x - y * y);
    sh[10] = 2.890611f * x * y * z;
    sh[11] = 0.457046f * y * (5.0f * z * z - 1.0f);
    sh[12] = 0.373176f * z * (5.0f * z * z - 3.0f);
    sh[13] = 0.457046f * x * (5.0f * z * z - 1.0f);
    sh[14] = 1.445306f * z * (x * x - y * y);
    sh[15] = 0.590044f * x * (x * x - 3.0f * y * y);
}

// 128 threads, each owns TWO rays (r0 = blk*256 + tid, r1 = r0 + 128).
// Coefficients read once per point per thread via LDS.128 broadcast, used by both rays.
__global__ void __launch_bounds__(128, 4)
main_k(const float* __restrict__ sh_coeffs) {
    int tid   = threadIdx.x;
    int r0    = blockIdx.x * 256 + tid;
    int r1    = r0 + 128;
    int chunk = blockIdx.y;

    float4 oA = g_ro[r0], oB = g_ro[r1];
    float4 dA = g_dn[r0], dB = g_dn[r1];
    float shA[16], shB[16];
#pragma unroll
    for (int k = 0; k < 16; k++) { shA[k] = g_sh[r0*16 + k]; shB[k] = g_sh[r1*16 + k]; }

    float SA = 0, arA = 0, agA = 0, abA = 0, adA = 0;
    float SB = 0, arB = 0, agB = 0, abB = 0, adB = 0;

    __shared__ float4 s_pt[TILE];
    __shared__ float  s_sf[TILE];
    __shared__ float4 s_cf[TILE * 12];   // 48 floats per point as 12 float4

    int p0 = chunk * PPC;
    for (int base = p0; base < p0 + PPC; base += TILE) {
        int cnt = min(TILE, p0 + PPC - base);
        __syncthreads();
        for (int i = tid; i < cnt; i += 128) {
            s_pt[i] = g_pt[base + i];
            s_sf[i] = g_sf[base + i];
        }
        const float4* src = (const float4*)(sh_coeffs + (size_t)base * 48);
        for (int i = tid; i < cnt * 12; i += 128) s_cf[i] = src[i];
        __syncthreads();

        for (int j = 0; j < cnt; j++) {
            float4 p = s_pt[j];
            float sf = s_sf[j];

            // geometry, ray A
            float rxA = p.x - oA.x, ryA = p.y - oA.y, rzA = p.z - oA.z;
            float d2A  = rxA*rxA + ryA*ryA + rzA*rzA;
            float riA  = rsqrtf(d2A);                 // == 1/dist (eps ~1e-6 rel, within budget)
            float distA = d2A * riA;
            float dotA = (rxA*dA.x + ryA*dA.y + rzA*dA.z) * riA;
            float tA   = 1.0f - dotA;
            float wA   = __expf(-p.w * tA * tA) * sf * riA;

            // geometry, ray B
            float rxB = p.x - oB.x, ryB = p.y - oB.y, rzB = p.z - oB.z;
            float d2B  = rxB*rxB + ryB*ryB + rzB*rzB;
            float riB  = rsqrtf(d2B);
            float distB = d2B * riB;
            float dotB = (rxB*dB.x + ryB*dB.y + rzB*dB.z) * riB;
            float tB   = 1.0f - dotB;
            float wB   = __expf(-p.w * tB * tB) * sf * riB;

            // SH logits for both rays, coefficients via LDS.128 broadcast
            float lA0 = 0, lA1 = 0, lA2 = 0;
            float lB0 = 0, lB1 = 0, lB2 = 0;
            const float4* cf4 = &s_cf[j * 12];
#pragma unroll
            for (int q = 0; q < 12; q++) {
                float4 c = cf4[q];
                float cv[4] = {c.x, c.y, c.z, c.w};
#pragma unroll
                for (int e = 0; e < 4; e++) {
                    const int idx = 4*q + e;
                    const int k  = idx / 3;
                    const int ch = idx - 3*k;
                    if (ch == 0) { lA0 += cv[e] * shA[k]; lB0 += cv[e] * shB[k]; }
                    if (ch == 1) { lA1 += cv[e] * shA[k]; lB1 += cv[e] * shB[k]; }
                    if (ch == 2) { lA2 += cv[e] * shA[k]; lB2 += cv[e] * shB[k]; }
                }
            }

            SA += wA;  adA += wA * distA;
            arA += wA * fsigmoid(lA0);
            agA += wA * fsigmoid(lA1);
            abA += wA * fsigmoid(lA2);

            SB += wB;  adB += wB * distB;
            arB += wB * fsigmoid(lB0);
            agB += wB * fsigmoid(lB1);
            abB += wB * fsigmoid(lB2);
        }
    }

    int iA = chunk * NR + r0;
    g_part[0 * NCHUNK * NR + iA] = SA;
    g_part[1 * NCHUNK * NR + iA] = arA;
    g_part[2 * NCHUNK * NR + iA] = agA;
    g_part[3 * NCHUNK * NR + iA] = abA;
    g_part[4 * NCHUNK * NR + iA] = adA;
    int iB = chunk * NR + r1;
    g_part[0 * NCHUNK * NR + iB] = SB;
    g_part[1 * NCHUNK * NR + iB] = arB;
    g_part[2 * NCHUNK * NR + iB] = agB;
    g_part[3 * NCHUNK * NR + iB] = abB;
    g_part[4 * NCHUNK * NR + iB] = adB;
}

__global__ void finalize(float* __restrict__ out) {
    int ray = blockIdx.x * 256 + threadIdx.x;
    if (ray >= NR) return;
    float S = 0, ar = 0, ag = 0, ab = 0, ad = 0;
#pragma unroll
    for (int c = 0; c < NCHUNK; c++) {
        int idx = c * NR + ray;
        S  += g_part[0 * NCHUNK * NR + idx];
        ar += g_part[1 * NCHUNK * NR + idx];
        ag += g_part[2 * NCHUNK * NR + idx];
        ab += g_part[3 * NCHUNK * NR + idx];
        ad += g_part[4 * NCHUNK * NR + idx];
    }
    float inv = __fdividef(1.0f, S + 1e-8f);
    out[ray*3 + 0] = ar * inv;
    out[ray*3 + 1] = ag * inv;
    out[ray*3 + 2] = ab * inv;
    out[3*NR + ray] = ad * inv;   // depth
    out[4*NR + ray] = g_opmean;   // opac (broadcast mean opacity)
}

extern "C" void kernel_launch(void* const* d_in, const int* in_sizes, int n_in,
                              void* d_out, int out_size) {
    const float* rays_o    = (const float*)d_in[0];
    const float* rays_d    = (const float*)d_in[1];
    const float* positions = (const float*)d_in[2];
    const int*   sidx      = (const int*)  d_in[3];
    const float* log_delta = (const float*)d_in[4];
    const float* log_sigma = (const float*)d_in[5];
    const float* raw_op    = (const float*)d_in[6];
    const float* shc       = (const float*)d_in[7];
    float* out = (float*)d_out;

    prep_points<<<(NP + 255) / 256, 256>>>(positions, sidx, log_delta, log_sigma, raw_op);
    op_mean_k<<<1, 256>>>(raw_op);
    prep_rays<<<NR / 256, 256>>>(rays_o, rays_d);
    main_k<<<dim3(16, NCHUNK), 128>>>(shc);
    finalize<<<NR / 256, 256>>>(out);
}

// round 6
// speedup vs baseline: 1.5860x; 1.3182x over previous
#include <cuda_runtime.h>

#define NP 10000
#define NR 4096
#define NCHUNK 40
#define PPC 250     // points per chunk (NCHUNK * PPC == NP)
#define TILE 64

typedef unsigned long long ull;

// ---- static scratch (no allocations allowed) ----
__device__ float4 g_pt[NP];          // pos.xyz, delta
__device__ float  g_sf[NP];          // sigma * opacity
__device__ float4 g_ro[NR];          // ray origin
__device__ float4 g_dn[NR];          // normalized dir
__device__ float  g_sh[NR * 16];     // SH basis per ray
__device__ float  g_part[5 * NCHUNK * NR];
__device__ float  g_opmean;

__device__ __forceinline__ float fsigmoid(float x) { return __fdividef(1.0f, 1.0f + __expf(-x)); }

// ---- packed f32x2 helpers (sm_103a) ----
__device__ __forceinline__ ull pk2(float a, float b) {
    ull r; asm("mov.b64 %0, {%1, %2};" : "=l"(r) : "f"(a), "f"(b)); return r;
}
__device__ __forceinline__ void fma2(ull& d, ull a, ull b) {
    asm("fma.rn.f32x2 %0, %1, %2, %0;" : "+l"(d) : "l"(a), "l"(b));
}
__device__ __forceinline__ float2 unpk2(ull v) {
    float2 r; asm("mov.b64 {%0, %1}, %2;" : "=f"(r.x), "=f"(r.y) : "l"(v)); return r;
}

__global__ void prep_points(const float* __restrict__ positions,
                            const int*   __restrict__ sidx,
                            const float* __restrict__ log_delta,
                            const float* __restrict__ log_sigma,
                            const float* __restrict__ raw_op) {
    int i = blockIdx.x * blockDim.x + threadIdx.x;
    if (i >= NP) return;
    int s = sidx[i];
    float delta = __expf(log_delta[s]);
    float sigma = __expf(log_sigma[s]);
    float op    = fsigmoid(raw_op[i]);
    g_pt[i] = make_float4(positions[i*3+0], positions[i*3+1], positions[i*3+2], delta);
    g_sf[i] = sigma * op;
}

__global__ void op_mean_k(const float* __restrict__ raw_op) {
    __shared__ float red[256];
    float s = 0.0f;
    for (int i = threadIdx.x; i < NP; i += 256) s += fsigmoid(raw_op[i]);
    red[threadIdx.x] = s;
    __syncthreads();
    for (int o = 128; o > 0; o >>= 1) {
        if (threadIdx.x < o) red[threadIdx.x] += red[threadIdx.x + o];
        __syncthreads();
    }
    if (threadIdx.x == 0) g_opmean = red[0] * (1.0f / (float)NP);
}

__global__ void prep_rays(const float* __restrict__ rays_o,
                          const float* __restrict__ rays_d) {
    int i = blockIdx.x * blockDim.x + threadIdx.x;
    if (i >= NR) return;
    float ox = rays_o[i*3+0], oy = rays_o[i*3+1], oz = rays_o[i*3+2];
    float dx = rays_d[i*3+0], dy = rays_d[i*3+1], dz = rays_d[i*3+2];
    float inv = rsqrtf(dx*dx + dy*dy + dz*dz);
    float x = dx * inv, y = dy * inv, z = dz * inv;
    g_ro[i] = make_float4(ox, oy, oz, 0.0f);
    g_dn[i] = make_float4(x, y, z, 0.0f);
    float* sh = &g_sh[i * 16];
    sh[0]  = 0.282095f;
    sh[1]  = 0.488603f * y;
    sh[2]  = 0.488603f * z;
    sh[3]  = 0.488603f * x;
    sh[4]  = 1.092548f * x * y;
    sh[5]  = 1.092548f * y * z;
    sh[6]  = 0.315392f * (3.0f * z * z - 1.0f);
    sh[7]  = 1.092548f * x * z;
    sh[8]  = 0.546274f * (x * x - y * y);
    sh[9]  = 0.590044f * y * (3.0f * x * x - y * y);
    sh[10] = 2.890611f * x * y * z;
    sh[11] = 0.457046f * y * (5.0f * z * z - 1.0f);
    sh[12] = 0.373176f * z * (5.0f * z * z - 3.0f);
    sh[13] = 0.457046f * x * (5.0f * z * z - 1.0f);
    sh[14] = 1.445306f * z * (x * x - y * y);
    sh[15] = 0.590044f * x * (x * x - 3.0f * y * y);
}

// 128 threads, one ray each. SH logits via packed fma.rn.f32x2:
// coeff memory layout (k0c0,k0c1,k0c2,k1c0,k1c1,k1c2,...) pairs naturally into
// f32x2 operands; sh broadcast patterns (sk,sk),(sk,sk'),(sk',sk') pre-packed.
__global__ void __launch_bounds__(128, 4)
main_k(const float* __restrict__ sh_coeffs) {
    int tid   = threadIdx.x;
    int ray   = blockIdx.x * 128 + tid;
    int chunk = blockIdx.y;

    float4 o4 = g_ro[ray];
    float4 d4 = g_dn[ray];

    // pre-packed sh patterns: 8 groups x 3 packed words
    ull q[24];
    {
        float sh[16];
#pragma unroll
        for (int k = 0; k < 16; k++) sh[k] = g_sh[ray*16 + k];
#pragma unroll
        for (int g = 0; g < 8; g++) {
            float a = sh[2*g], b = sh[2*g + 1];
            q[3*g + 0] = pk2(a, a);
            q[3*g + 1] = pk2(a, b);
            q[3*g + 2] = pk2(b, b);
        }
    }

    float S = 0, ar = 0, ag = 0, ab = 0, ad = 0;

    __shared__ float4 s_pt[TILE];
    __shared__ float  s_sf[TILE];
    __shared__ ull    s_cf[TILE * 24];   // 48 floats/point = 24 packed u64

    int p0 = chunk * PPC;
    for (int base = p0; base < p0 + PPC; base += TILE) {
        int cnt = min(TILE, p0 + PPC - base);
        __syncthreads();
        for (int i = tid; i < cnt; i += 128) {
            s_pt[i] = g_pt[base + i];
            s_sf[i] = g_sf[base + i];
        }
        const ulonglong2* src = (const ulonglong2*)(sh_coeffs + (size_t)base * 48);
        ulonglong2* dst = (ulonglong2*)s_cf;
        for (int i = tid; i < cnt * 12; i += 128) dst[i] = src[i];
        __syncthreads();

        for (int j = 0; j < cnt; j++) {
            float4 p = s_pt[j];
            float rx = p.x - o4.x, ry = p.y - o4.y, rz = p.z - o4.z;
            float d2   = rx*rx + ry*ry + rz*rz;
            float ri   = rsqrtf(d2);              // == 1/dist within fp budget
            float dist = d2 * ri;
            float dot  = (rx*d4.x + ry*d4.y + rz*d4.z) * ri;
            float t    = 1.0f - dot;
            float w    = __expf(-p.w * t * t) * s_sf[j] * ri;

            // packed SH logits
            ull a0 = 0ULL, a1 = 0ULL, a2 = 0ULL;
            const ulonglong2* cf2 = (const ulonglong2*)&s_cf[j * 24];
#pragma unroll
            for (int sg = 0; sg < 4; sg++) {
                ulonglong2 t0 = cf2[3*sg + 0];
                ulonglong2 t1 = cf2[3*sg + 1];
                ulonglong2 t2 = cf2[3*sg + 2];
                fma2(a0, t0.x, q[6*sg + 0]);
                fma2(a1, t0.y, q[6*sg + 1]);
                fma2(a2, t1.x, q[6*sg + 2]);
                fma2(a0, t1.y, q[6*sg + 3]);
                fma2(a1, t2.x, q[6*sg + 4]);
                fma2(a2, t2.y, q[6*sg + 5]);
            }
            float2 f0 = unpk2(a0);   // (l0 part, l1 part)
            float2 f1 = unpk2(a1);   // (l2 part, l0 part)
            float2 f2 = unpk2(a2);   // (l1 part, l2 part)
            float l0 = f0.x + f1.y;
            float l1 = f0.y + f2.x;
            float l2 = f1.x + f2.y;

            S  += w;
            ad += w * dist;
            ar += w * fsigmoid(l0);
            ag += w * fsigmoid(l1);
            ab += w * fsigmoid(l2);
        }
    }

    int idx = chunk * NR + ray;
    g_part[0 * NCHUNK * NR + idx] = S;
    g_part[1 * NCHUNK * NR + idx] = ar;
    g_part[2 * NCHUNK * NR + idx] = ag;
    g_part[3 * NCHUNK * NR + idx] = ab;
    g_part[4 * NCHUNK * NR + idx] = ad;
}

__global__ void finalize(float* __restrict__ out) {
    int ray = blockIdx.x * 256 + threadIdx.x;
    if (ray >= NR) return;
    float S = 0, ar = 0, ag = 0, ab = 0, ad = 0;
#pragma unroll
    for (int c = 0; c < NCHUNK; c++) {
        int idx = c * NR + ray;
        S  += g_part[0 * NCHUNK * NR + idx];
        ar += g_part[1 * NCHUNK * NR + idx];
        ag += g_part[2 * NCHUNK * NR + idx];
        ab += g_part[3 * NCHUNK * NR + idx];
        ad += g_part[4 * NCHUNK * NR + idx];
    }
    float inv = __fdividef(1.0f, S + 1e-8f);
    out[ray*3 + 0] = ar * inv;
    out[ray*3 + 1] = ag * inv;
    out[ray*3 + 2] = ab * inv;
    out[3*NR + ray] = ad * inv;   // depth
    out[4*NR + ray] = g_opmean;   // opac (broadcast mean opacity)
}

extern "C" void kernel_launch(void* const* d_in, const int* in_sizes, int n_in,
                              void* d_out, int out_size) {
    const float* rays_o    = (const float*)d_in[0];
    const float* rays_d    = (const float*)d_in[1];
    const float* positions = (const float*)d_in[2];
    const int*   sidx      = (const int*)  d_in[3];
    const float* log_delta = (const float*)d_in[4];
    const float* log_sigma = (const float*)d_in[5];
    const float* raw_op    = (const float*)d_in[6];
    const float* shc       = (const float*)d_in[7];
    float* out = (float*)d_out;

    prep_points<<<(NP + 255) / 256, 256>>>(positions, sidx, log_delta, log_sigma, raw_op);
    op_mean_k<<<1, 256>>>(raw_op);
    prep_rays<<<NR / 256, 256>>>(rays_o, rays_d);
    main_k<<<dim3(NR / 128, NCHUNK), 128>>>(shc);
    finalize<<<NR / 256, 256>>>(out);
}

// round 7
// speedup vs baseline: 1.7064x; 1.0759x over previous
#include <cuda_runtime.h>

#define NP 10000
#define NR 4096
#define NCHUNK 80
#define PPC 125     // points per chunk (NCHUNK * PPC == NP)
#define TILE 64

typedef unsigned long long ull;

// ---- static scratch (no allocations allowed) ----
__device__ float4 g_pt[NP];          // pos.xyz, -delta*log2e
__device__ float  g_sf[NP];          // sigma * opacity
__device__ ull    g_cf[NP * 24];     // planar packed half-coeffs: [pt][c*8+g] = (0.5*cf[2g][c], 0.5*cf[2g+1][c])
__device__ float4 g_ro[NR];          // ray origin
__device__ float4 g_dn[NR];          // normalized dir
__device__ float  g_sh[NR * 16];     // SH basis per ray (pairs are f32x2-ready)
__device__ float  g_part[5 * NCHUNK * NR];
__device__ float  g_opmean;

__device__ __forceinline__ float fsigmoid(float x) { return __fdividef(1.0f, 1.0f + __expf(-x)); }

// ---- packed f32x2 helpers (sm_103a) ----
__device__ __forceinline__ ull pk2(float a, float b) {
    ull r; asm("mov.b64 %0, {%1, %2};" : "=l"(r) : "f"(a), "f"(b)); return r;
}
__device__ __forceinline__ void fma2(ull& d, ull a, ull b) {
    asm("fma.rn.f32x2 %0, %1, %2, %0;" : "+l"(d) : "l"(a), "l"(b));
}
__device__ __forceinline__ ull mul2(ull a, ull b) {
    ull d; asm("mul.rn.f32x2 %0, %1, %2;" : "=l"(d) : "l"(a), "l"(b)); return d;
}
__device__ __forceinline__ ull add2(ull a, ull b) {
    ull d; asm("add.rn.f32x2 %0, %1, %2;" : "=l"(d) : "l"(a), "l"(b)); return d;
}
__device__ __forceinline__ float2 unpk2(ull v) {
    float2 r; asm("mov.b64 {%0, %1}, %2;" : "=f"(r.x), "=f"(r.y) : "l"(v)); return r;
}
__device__ __forceinline__ float tanhfast(float x) {
    float y; asm("tanh.approx.f32 %0, %1;" : "=f"(y) : "f"(x)); return y;
}
__device__ __forceinline__ float ex2fast(float x) {
    float y; asm("ex2.approx.f32 %0, %1;" : "=f"(y) : "f"(x)); return y;
}

__global__ void prep_points(const float* __restrict__ positions,
                            const int*   __restrict__ sidx,
                            const float* __restrict__ log_delta,
                            const float* __restrict__ log_sigma,
                            const float* __restrict__ raw_op) {
    int i = blockIdx.x * blockDim.x + threadIdx.x;
    if (i >= NP) return;
    int s = sidx[i];
    float delta = __expf(log_delta[s]);
    float sigma = __expf(log_sigma[s]);
    float op    = fsigmoid(raw_op[i]);
    // fold -log2(e) so the Gaussian is a single ex2
    g_pt[i] = make_float4(positions[i*3+0], positions[i*3+1], positions[i*3+2],
                          -delta * 1.4426950408889634f);
    g_sf[i] = sigma * op;
}

// channel-planar packed coefficient transpose, pre-scaled by 0.5 for the tanh sigmoid
__global__ void prep_cf(const float* __restrict__ shc) {
    int i = blockIdx.x * blockDim.x + threadIdx.x;
    if (i >= NP * 24) return;
    int pt = i / 24, w = i % 24;
    int c = w >> 3, g = w & 7;
    const float* b = shc + (size_t)pt * 48;
    g_cf[i] = pk2(0.5f * b[(2*g)*3 + c], 0.5f * b[(2*g+1)*3 + c]);
}

__global__ void op_mean_k(const float* __restrict__ raw_op) {
    __shared__ float red[256];
    float s = 0.0f;
    for (int i = threadIdx.x; i < NP; i += 256) s += fsigmoid(raw_op[i]);
    red[threadIdx.x] = s;
    __syncthreads();
    for (int o = 128; o > 0; o >>= 1) {
        if (threadIdx.x < o) red[threadIdx.x] += red[threadIdx.x + o];
        __syncthreads();
    }
    if (threadIdx.x == 0) g_opmean = red[0] * (1.0f / (float)NP);
}

__global__ void prep_rays(const float* __restrict__ rays_o,
                          const float* __restrict__ rays_d) {
    int i = blockIdx.x * blockDim.x + threadIdx.x;
    if (i >= NR) return;
    float ox = rays_o[i*3+0], oy = rays_o[i*3+1], oz = rays_o[i*3+2];
    float dx = rays_d[i*3+0], dy = rays_d[i*3+1], dz = rays_d[i*3+2];
    float inv = rsqrtf(dx*dx + dy*dy + dz*dz);
    float x = dx * inv, y = dy * inv, z = dz * inv;
    g_ro[i] = make_float4(ox, oy, oz, 0.0f);
    g_dn[i] = make_float4(x, y, z, 0.0f);
    float* sh = &g_sh[i * 16];
    sh[0]  = 0.282095f;
    sh[1]  = 0.488603f * y;
    sh[2]  = 0.488603f * z;
    sh[3]  = 0.488603f * x;
    sh[4]  = 1.092548f * x * y;
    sh[5]  = 1.092548f * y * z;
    sh[6]  = 0.315392f * (3.0f * z * z - 1.0f);
    sh[7]  = 1.092548f * x * z;
    sh[8]  = 0.546274f * (x * x - y * y);
    sh[9]  = 0.590044f * y * (3.0f * x * x - y * y);
    sh[10] = 2.890611f * x * y * z;
    sh[11] = 0.457046f * y * (5.0f * z * z - 1.0f);
    sh[12] = 0.373176f * z * (5.0f * z * z - 3.0f);
    sh[13] = 0.457046f * x * (5.0f * z * z - 1.0f);
    sh[14] = 1.445306f * z * (x * x - y * y);
    sh[15] = 0.590044f * x * (x * x - 3.0f * y * y);
}

// 128 threads, TWO rays per thread (r0 = blk*256+tid, r1 = r0+128).
// Coefficient LDS shared across both rays; SH dot fully packed fma.rn.f32x2;
// geometry packed (rayA,rayB); sigmoid via tanh.approx; gaussian via ex2.approx.
__global__ void __launch_bounds__(128, 4)
main_k() {
    int tid   = threadIdx.x;
    int r0    = blockIdx.x * 256 + tid;
    int r1    = r0 + 128;
    int chunk = blockIdx.y;

    float4 oA = g_ro[r0], oB = g_ro[r1];
    float4 dA = g_dn[r0], dB = g_dn[r1];
    ull nox = pk2(-oA.x, -oB.x), noy = pk2(-oA.y, -oB.y), noz = pk2(-oA.z, -oB.z);
    ull ddx = pk2(dA.x, dB.x),  ddy = pk2(dA.y, dB.y),  ddz = pk2(dA.z, dB.z);

    ull shA[8], shB[8];
    {
        const ull* sp = (const ull*)g_sh;
#pragma unroll
        for (int g = 0; g < 8; g++) { shA[g] = sp[r0*8 + g]; shB[g] = sp[r1*8 + g]; }
    }

    float SA = 0, arA = 0, agA = 0, abA = 0, adA = 0;
    float SB = 0, arB = 0, agB = 0, abB = 0, adB = 0;

    __shared__ float4 s_pt[TILE];
    __shared__ float  s_sf[TILE];
    __shared__ ull    s_cf[TILE * 24];

    int p0 = chunk * PPC;
    for (int base = p0; base < p0 + PPC; base += TILE) {
        int cnt = min(TILE, p0 + PPC - base);
        __syncthreads();
        for (int i = tid; i < cnt; i += 128) {
            s_pt[i] = g_pt[base + i];
            s_sf[i] = g_sf[base + i];
        }
        const ulonglong2* src = (const ulonglong2*)(g_cf + (size_t)base * 24);
        ulonglong2* dst = (ulonglong2*)s_cf;
        for (int i = tid; i < cnt * 12; i += 128) dst[i] = src[i];
        __syncthreads();

        for (int j = 0; j < cnt; j++) {
            float4 p = s_pt[j];
            float sf = s_sf[j];

            // packed geometry for both rays
            ull px = pk2(p.x, p.x), py = pk2(p.y, p.y), pz = pk2(p.z, p.z);
            ull rx = add2(px, nox), ry = add2(py, noy), rz = add2(pz, noz);
            ull d2p = mul2(rx, rx); fma2(d2p, ry, ry); fma2(d2p, rz, rz);
            ull dtp = mul2(rx, ddx); fma2(dtp, ry, ddy); fma2(dtp, rz, ddz);
            float2 d2 = unpk2(d2p), dt = unpk2(dtp);

            float riA = rsqrtf(d2.x);
            float distA = d2.x * riA;
            float tA  = fmaf(-dt.x, riA, 1.0f);
            float wA  = ex2fast(p.w * (tA * tA)) * sf * riA;

            float riB = rsqrtf(d2.y);
            float distB = d2.y * riB;
            float tB  = fmaf(-dt.y, riB, 1.0f);
            float wB  = ex2fast(p.w * (tB * tB)) * sf * riB;

            // packed SH half-logits, channel-planar coefficients
            ull aA0 = 0, aA1 = 0, aA2 = 0, aB0 = 0, aB1 = 0, aB2 = 0;
            const ulonglong2* cf = (const ulonglong2*)&s_cf[j * 24];
#pragma unroll
            for (int h = 0; h < 4; h++) {
                ulonglong2 c0 = cf[0*4 + h];
                fma2(aA0, c0.x, shA[2*h]); fma2(aA0, c0.y, shA[2*h+1]);
                fma2(aB0, c0.x, shB[2*h]); fma2(aB0, c0.y, shB[2*h+1]);
                ulonglong2 c1 = cf[1*4 + h];
                fma2(aA1, c1.x, shA[2*h]); fma2(aA1, c1.y, shA[2*h+1]);
                fma2(aB1, c1.x, shB[2*h]); fma2(aB1, c1.y, shB[2*h+1]);
                ulonglong2 c2 = cf[2*4 + h];
                fma2(aA2, c2.x, shA[2*h]); fma2(aA2, c2.y, shA[2*h+1]);
                fma2(aB2, c2.x, shB[2*h]); fma2(aB2, c2.y, shB[2*h+1]);
            }

            // sigmoid(l) = 0.5 + 0.5*tanh(l/2); coeffs pre-scaled by 0.5, so sums ARE l/2
            float2 f;
            f = unpk2(aA0); float cA0 = fmaf(0.5f, tanhfast(f.x + f.y), 0.5f);
            f = unpk2(aA1); float cA1 = fmaf(0.5f, tanhfast(f.x + f.y), 0.5f);
            f = unpk2(aA2); float cA2 = fmaf(0.5f, tanhfast(f.x + f.y), 0.5f);
            f = unpk2(aB0); float cB0 = fmaf(0.5f, tanhfast(f.x + f.y), 0.5f);
            f = unpk2(aB1); float cB1 = fmaf(0.5f, tanhfast(f.x + f.y), 0.5f);
            f = unpk2(aB2); float cB2 = fmaf(0.5f, tanhfast(f.x + f.y), 0.5f);

            SA += wA; adA = fmaf(wA, distA, adA);
            arA = fmaf(wA, cA0, arA); agA = fmaf(wA, cA1, agA); abA = fmaf(wA, cA2, abA);
            SB += wB; adB = fmaf(wB, distB, adB);
            arB = fmaf(wB, cB0, arB); agB = fmaf(wB, cB1, agB); abB = fmaf(wB, cB2, abB);
        }
    }

    int iA = chunk * NR + r0;
    g_part[0 * NCHUNK * NR + iA] = SA;
    g_part[1 * NCHUNK * NR + iA] = arA;
    g_part[2 * NCHUNK * NR + iA] = agA;
    g_part[3 * NCHUNK * NR + iA] = abA;
    g_part[4 * NCHUNK * NR + iA] = adA;
    int iB = chunk * NR + r1;
    g_part[0 * NCHUNK * NR + iB] = SB;
    g_part[1 * NCHUNK * NR + iB] = arB;
    g_part[2 * NCHUNK * NR + iB] = agB;
    g_part[3 * NCHUNK * NR + iB] = abB;
    g_part[4 * NCHUNK * NR + iB] = adB;
}

__global__ void finalize(float* __restrict__ out) {
    int ray = blockIdx.x * 256 + threadIdx.x;
    if (ray >= NR) return;
    float S = 0, ar = 0, ag = 0, ab = 0, ad = 0;
    for (int c = 0; c < NCHUNK; c++) {
        int idx = c * NR + ray;
        S  += g_part[0 * NCHUNK * NR + idx];
        ar += g_part[1 * NCHUNK * NR + idx];
        ag += g_part[2 * NCHUNK * NR + idx];
        ab += g_part[3 * NCHUNK * NR + idx];
        ad += g_part[4 * NCHUNK * NR + idx];
    }
    float inv = __fdividef(1.0f, S + 1e-8f);
    out[ray*3 + 0] = ar * inv;
    out[ray*3 + 1] = ag * inv;
    out[ray*3 + 2] = ab * inv;
    out[3*NR + ray] = ad * inv;   // depth
    out[4*NR + ray] = g_opmean;   // opac (broadcast mean opacity)
}

extern "C" void kernel_launch(void* const* d_in, const int* in_sizes, int n_in,
                              void* d_out, int out_size) {
    const float* rays_o    = (const float*)d_in[0];
    const float* rays_d    = (const float*)d_in[1];
    const float* positions = (const float*)d_in[2];
    const int*   sidx      = (const int*)  d_in[3];
    const float* log_delta = (const float*)d_in[4];
    const float* log_sigma = (const float*)d_in[5];
    const float* raw_op    = (const float*)d_in[6];
    const float* shc       = (const float*)d_in[7];
    float* out = (float*)d_out;

    prep_points<<<(NP + 255) / 256, 256>>>(positions, sidx, log_delta, log_sigma, raw_op);
    prep_cf<<<(NP * 24 + 255) / 256, 256>>>(shc);
    op_mean_k<<<1, 256>>>(raw_op);
    prep_rays<<<NR / 256, 256>>>(rays_o, rays_d);
    main_k<<<dim3(NR / 256, NCHUNK), 128>>>();
    finalize<<<NR / 256, 256>>>(out);
}

// round 10
// speedup vs baseline: 1.9635x; 1.1507x over previous
#include <cuda_runtime.h>
#include <cuda_fp16.h>

#define NP 10000
#define NR 4096
#define NCHUNK 80
#define PPC 125     // points per chunk (NCHUNK * PPC == NP)
#define TILE 64

typedef unsigned long long ull;
typedef unsigned int u32;

// ---- static scratch (no allocations allowed) ----
__device__ float4 g_pt[NP];          // pos.xyz, -delta*log2e
__device__ float  g_sf[NP];          // sigma * opacity
__device__ u32    g_cf[NP * 24];     // [pt][c*8+g] = half2(0.5*cf[2g][c], 0.5*cf[2g+1][c])
__device__ float4 g_ro[NR];
__device__ float4 g_dn[NR];
__device__ __half g_shh[NR * 16];    // fp16 SH basis per ray
__device__ float  g_part[5 * NCHUNK * NR];
__device__ float  g_opmean;

__device__ __forceinline__ float fsigmoid(float x) { return __fdividef(1.0f, 1.0f + __expf(-x)); }

// ---- packed f32x2 helpers (sm_103a) ----
__device__ __forceinline__ ull pk2(float a, float b) {
    ull r; asm("mov.b64 %0, {%1, %2};" : "=l"(r) : "f"(a), "f"(b)); return r;
}
__device__ __forceinline__ void fma2(ull& d, ull a, ull b) {
    asm("fma.rn.f32x2 %0, %1, %2, %0;" : "+l"(d) : "l"(a), "l"(b));
}
__device__ __forceinline__ ull mul2(ull a, ull b) {
    ull d; asm("mul.rn.f32x2 %0, %1, %2;" : "=l"(d) : "l"(a), "l"(b)); return d;
}
__device__ __forceinline__ ull add2(ull a, ull b) {
    ull d; asm("add.rn.f32x2 %0, %1, %2;" : "=l"(d) : "l"(a), "l"(b)); return d;
}
__device__ __forceinline__ float2 unpk2(ull v) {
    float2 r; asm("mov.b64 {%0, %1}, %2;" : "=f"(r.x), "=f"(r.y) : "l"(v)); return r;
}
__device__ __forceinline__ float ex2fast(float x) {
    float y; asm("ex2.approx.f32 %0, %1;" : "=f"(y) : "f"(x)); return y;
}
__device__ __forceinline__ __half2 tanh2fast(__half2 x) {
    __half2 y;
    asm("tanh.approx.f16x2 %0, %1;" : "=r"(*(u32*)&y) : "r"(*(const u32*)&x));
    return y;
}

__global__ void prep_points(const float* __restrict__ positions,
                            const int*   __restrict__ sidx,
                            const float* __restrict__ log_delta,
                            const float* __restrict__ log_sigma,
                            const float* __restrict__ raw_op) {
    int i = blockIdx.x * blockDim.x + threadIdx.x;
    if (i >= NP) return;
    int s = sidx[i];
    float delta = __expf(log_delta[s]);
    float sigma = __expf(log_sigma[s]);
    float op    = fsigmoid(raw_op[i]);
    g_pt[i] = make_float4(positions[i*3+0], positions[i*3+1], positions[i*3+2],
                          -delta * 1.4426950408889634f);
    g_sf[i] = sigma * op;
}

// channel-planar fp16 half-coefficient packs: u32 g = half2(0.5*cf[2g][c], 0.5*cf[2g+1][c])
__global__ void prep_cf(const float* __restrict__ shc) {
    int i = blockIdx.x * blockDim.x + threadIdx.x;
    if (i >= NP * 24) return;
    int pt = i / 24, w = i % 24;
    int c = w >> 3, g = w & 7;
    const float* b = shc + (size_t)pt * 48;
    __half2 h = __floats2half2_rn(0.5f * b[(2*g)*3 + c], 0.5f * b[(2*g+1)*3 + c]);
    g_cf[i] = *(const u32*)&h;
}

__global__ void op_mean_k(const float* __restrict__ raw_op) {
    __shared__ float red[256];
    float s = 0.0f;
    for (int i = threadIdx.x; i < NP; i += 256) s += fsigmoid(raw_op[i]);
    red[threadIdx.x] = s;
    __syncthreads();
    for (int o = 128; o > 0; o >>= 1) {
        if (threadIdx.x < o) red[threadIdx.x] += red[threadIdx.x + o];
        __syncthreads();
    }
    if (threadIdx.x == 0) g_opmean = red[0] * (1.0f / (float)NP);
}

__global__ void prep_rays(const float* __restrict__ rays_o,
                          const float* __restrict__ rays_d) {
    int i = blockIdx.x * blockDim.x + threadIdx.x;
    if (i >= NR) return;
    float ox = rays_o[i*3+0], oy = rays_o[i*3+1], oz = rays_o[i*3+2];
    float dx = rays_d[i*3+0], dy = rays_d[i*3+1], dz = rays_d[i*3+2];
    float inv = rsqrtf(dx*dx + dy*dy + dz*dz);
    float x = dx * inv, y = dy * inv, z = dz * inv;
    g_ro[i] = make_float4(ox, oy, oz, 0.0f);
    g_dn[i] = make_float4(x, y, z, 0.0f);
    float sh[16];
    sh[0]  = 0.282095f;
    sh[1]  = 0.488603f * y;
    sh[2]  = 0.488603f * z;
    sh[3]  = 0.488603f * x;
    sh[4]  = 1.092548f * x * y;
    sh[5]  = 1.092548f * y * z;
    sh[6]  = 0.315392f * (3.0f * z * z - 1.0f);
    sh[7]  = 1.092548f * x * z;
    sh[8]  = 0.546274f * (x * x - y * y);
    sh[9]  = 0.590044f * y * (3.0f * x * x - y * y);
    sh[10] = 2.890611f * x * y * z;
    sh[11] = 0.457046f * y * (5.0f * z * z - 1.0f);
    sh[12] = 0.373176f * z * (5.0f * z * z - 3.0f);
    sh[13] = 0.457046f * x * (5.0f * z * z - 1.0f);
    sh[14] = 1.445306f * z * (x * x - y * y);
    sh[15] = 0.590044f * x * (x * x - 3.0f * y * y);
#pragma unroll
    for (int k = 0; k < 16; k++) g_shh[i*16 + k] = __float2half(sh[k]);
}

// 128 threads, TWO rays/thread (r0 = blk*256+tid, r1 = r0+128).
// SH logits: fp16 HFMA2, half2 lanes = (rayA, rayB); 16 HFMA2 per channel per point.
// Geometry: packed f32x2. Sigmoid: tanh.approx.f16x2 (coeffs pre-scaled by 0.5).
__global__ void __launch_bounds__(128, 4)
main_k() {
    int tid   = threadIdx.x;
    int r0    = blockIdx.x * 256 + tid;
    int r1    = r0 + 128;
    int chunk = blockIdx.y;

    float4 oA = g_ro[r0], oB = g_ro[r1];
    float4 dA = g_dn[r0], dB = g_dn[r1];
    ull nox = pk2(-oA.x, -oB.x), noy = pk2(-oA.y, -oB.y), noz = pk2(-oA.z, -oB.z);
    ull ddx = pk2(dA.x, dB.x),  ddy = pk2(dA.y, dB.y),  ddz = pk2(dA.z, dB.z);

    // sh[k] = half2(shA[k], shB[k])
    __half2 sh[16];
#pragma unroll
    for (int k = 0; k < 16; k++)
        sh[k] = __halves2half2(g_shh[r0*16 + k], g_shh[r1*16 + k]);

    float SA = 0, arA = 0, agA = 0, abA = 0, adA = 0;
    float SB = 0, arB = 0, agB = 0, abB = 0, adB = 0;

    __shared__ float4 s_pt[TILE];
    __shared__ float  s_sf[TILE];
    __shared__ u32    s_cf[TILE * 24];

    const __half2 half05 = __floats2half2_rn(0.5f, 0.5f);

    int p0 = chunk * PPC;
    for (int base = p0; base < p0 + PPC; base += TILE) {
        int cnt = min(TILE, p0 + PPC - base);
        __syncthreads();
        for (int i = tid; i < cnt; i += 128) {
            s_pt[i] = g_pt[base + i];
            s_sf[i] = g_sf[base + i];
        }
        const uint4* src = (const uint4*)(g_cf + (size_t)base * 24);
        uint4* dst = (uint4*)s_cf;
        for (int i = tid; i < cnt * 6; i += 128) dst[i] = src[i];
        __syncthreads();

        for (int j = 0; j < cnt; j++) {
            float4 p = s_pt[j];
            float sf = s_sf[j];

            // packed geometry (rayA, rayB)
            ull px = pk2(p.x, p.x), py = pk2(p.y, p.y), pz = pk2(p.z, p.z);
            ull rx = add2(px, nox), ry = add2(py, noy), rz = add2(pz, noz);
            ull d2p = mul2(rx, rx); fma2(d2p, ry, ry); fma2(d2p, rz, rz);
            ull dtp = mul2(rx, ddx); fma2(dtp, ry, ddy); fma2(dtp, rz, ddz);
            float2 d2 = unpk2(d2p), dt = unpk2(dtp);

            float riA = rsqrtf(d2.x);
            float distA = d2.x * riA;
            float tA  = fmaf(-dt.x, riA, 1.0f);
            float wA  = ex2fast(p.w * (tA * tA)) * sf * riA;

            float riB = rsqrtf(d2.y);
            float distB = d2.y * riB;
            float tB  = fmaf(-dt.y, riB, 1.0f);
            float wB  = ex2fast(p.w * (tB * tB)) * sf * riB;

            // fp16 SH half-logits, lanes = (A,B); split even/odd chains per channel
            const uint4* cf = (const uint4*)&s_cf[j * 24];
            uint4 q0 = cf[0], q1 = cf[1];   // channel 0: k-pairs 0..7
            uint4 q2 = cf[2], q3 = cf[3];   // channel 1
            uint4 q4 = cf[4], q5 = cf[5];   // channel 2

            __half2 e0 = __floats2half2_rn(0.f,0.f), o0 = e0;
            __half2 e1 = e0, o1 = e0, e2 = e0, o2 = e0;
#define CH(acc_e, acc_o, qa, qb)                                              \
            {                                                                  \
                __half2 c;                                                     \
                c = *(const __half2*)&qa.x;                                    \
                acc_e = __hfma2(__low2half2(c),  sh[0], acc_e);                \
                acc_o = __hfma2(__high2half2(c), sh[1], acc_o);                \
                c = *(const __half2*)&qa.y;                                    \
                acc_e = __hfma2(__low2half2(c),  sh[2], acc_e);                \
                acc_o = __hfma2(__high2half2(c), sh[3], acc_o);                \
                c = *(const __half2*)&qa.z;                                    \
                acc_e = __hfma2(__low2half2(c),  sh[4], acc_e);                \
                acc_o = __hfma2(__high2half2(c), sh[5], acc_o);                \
                c = *(const __half2*)&qa.w;                                    \
                acc_e = __hfma2(__low2half2(c),  sh[6], acc_e);                \
                acc_o = __hfma2(__high2half2(c), sh[7], acc_o);                \
                c = *(const __half2*)&qb.x;                                    \
                acc_e = __hfma2(__low2half2(c),  sh[8], acc_e);                \
                acc_o = __hfma2(__high2half2(c), sh[9], acc_o);                \
                c = *(const __half2*)&qb.y;                                    \
                acc_e = __hfma2(__low2half2(c),  sh[10], acc_e);               \
                acc_o = __hfma2(__high2half2(c), sh[11], acc_o);               \
                c = *(const __half2*)&qb.z;                                    \
                acc_e = __hfma2(__low2half2(c),  sh[12], acc_e);               \
                acc_o = __hfma2(__high2half2(c), sh[13], acc_o);               \
                c = *(const __half2*)&qb.w;                                    \
                acc_e = __hfma2(__low2half2(c),  sh[14], acc_e);               \
                acc_o = __hfma2(__high2half2(c), sh[15], acc_o);               \
            }
            CH(e0, o0, q0, q1)
            CH(e1, o1, q2, q3)
            CH(e2, o2, q4, q5)
#undef CH
            // sigmoid(l) = 0.5 + 0.5*tanh(l/2); accs are l/2 (coeffs pre-scaled)
            __half2 col0 = __hfma2(half05, tanh2fast(__hadd2(e0, o0)), half05);
            __half2 col1 = __hfma2(half05, tanh2fast(__hadd2(e1, o1)), half05);
            __half2 col2 = __hfma2(half05, tanh2fast(__hadd2(e2, o2)), half05);

            SA += wA; adA = fmaf(wA, distA, adA);
            arA = fmaf(wA, __low2float(col0), arA);
            agA = fmaf(wA, __low2float(col1), agA);
            abA = fmaf(wA, __low2float(col2), abA);
            SB += wB; adB = fmaf(wB, distB, adB);
            arB = fmaf(wB, __high2float(col0), arB);
            agB = fmaf(wB, __high2float(col1), agB);
            abB = fmaf(wB, __high2float(col2), abB);
        }
    }

    int iA = chunk * NR + r0;
    g_part[0 * NCHUNK * NR + iA] = SA;
    g_part[1 * NCHUNK * NR + iA] = arA;
    g_part[2 * NCHUNK * NR + iA] = agA;
    g_part[3 * NCHUNK * NR + iA] = abA;
    g_part[4 * NCHUNK * NR + iA] = adA;
    int iB = chunk * NR + r1;
    g_part[0 * NCHUNK * NR + iB] = SB;
    g_part[1 * NCHUNK * NR + iB] = arB;
    g_part[2 * NCHUNK * NR + iB] = agB;
    g_part[3 * NCHUNK * NR + iB] = abB;
    g_part[4 * NCHUNK * NR + iB] = adB;
}

__global__ void finalize(float* __restrict__ out) {
    int ray = blockIdx.x * 256 + threadIdx.x;
    if (ray >= NR) return;
    float S = 0, ar = 0, ag = 0, ab = 0, ad = 0;
    for (int c = 0; c < NCHUNK; c++) {
        int idx = c * NR + ray;
        S  += g_part[0 * NCHUNK * NR + idx];
        ar += g_part[1 * NCHUNK * NR + idx];
        ag += g_part[2 * NCHUNK * NR + idx];
        ab += g_part[3 * NCHUNK * NR + idx];
        ad += g_part[4 * NCHUNK * NR + idx];
    }
    float inv = __fdividef(1.0f, S + 1e-8f);
    out[ray*3 + 0] = ar * inv;
    out[ray*3 + 1] = ag * inv;
    out[ray*3 + 2] = ab * inv;
    out[3*NR + ray] = ad * inv;   // depth
    out[4*NR + ray] = g_opmean;   // opac (broadcast mean opacity)
}

extern "C" void kernel_launch(void* const* d_in, const int* in_sizes, int n_in,
                              void* d_out, int out_size) {
    const float* rays_o    = (const float*)d_in[0];
    const float* rays_d    = (const float*)d_in[1];
    const float* positions = (const float*)d_in[2];
    const int*   sidx      = (const int*)  d_in[3];
    const float* log_delta = (const float*)d_in[4];
    const float* log_sigma = (const float*)d_in[5];
    const float* raw_op    = (const float*)d_in[6];
    const float* shc       = (const float*)d_in[7];
    float* out = (float*)d_out;

    prep_points<<<(NP + 255) / 256, 256>>>(positions, sidx, log_delta, log_sigma, raw_op);
    prep_cf<<<(NP * 24 + 255) / 256, 256>>>(shc);
    op_mean_k<<<1, 256>>>(raw_op);
    prep_rays<<<NR / 256, 256>>>(rays_o, rays_d);
    main_k<<<dim3(NR / 256, NCHUNK), 128>>>();
    finalize<<<NR / 256, 256>>>(out);
}

// round 13
// speedup vs baseline: 2.0123x; 1.0249x over previous
#include <cuda_runtime.h>
#include <cuda_fp16.h>

#define NP 10000
#define NR 4096
#define NCHUNK 80
#define PPC 125       // points per chunk == TILE (one smem fill per CTA)
#define TILE 125

typedef unsigned long long ull;
typedef unsigned int u32;

// ---- static scratch (no allocations allowed) ----
__device__ float4 g_pt[NP];          // pos.xyz, -delta*log2e
__device__ float  g_sf[NP];          // sigma * opacity
__device__ u32    g_cf[NP * 24];     // [pt][c*8+g] = half2(0.5*cf[2g][c], 0.5*cf[2g+1][c])
__device__ float4 g_ro[NR];
__device__ float4 g_dn[NR];
__device__ __half g_shh[NR * 16];    // fp16 SH basis per ray
__device__ float  g_part[5 * NCHUNK * NR];
__device__ float  g_opmean;

__device__ __forceinline__ float fsigmoid(float x) { return __fdividef(1.0f, 1.0f + __expf(-x)); }

// ---- packed f32x2 helpers (sm_103a) ----
__device__ __forceinline__ ull pk2(float a, float b) {
    ull r; asm("mov.b64 %0, {%1, %2};" : "=l"(r) : "f"(a), "f"(b)); return r;
}
__device__ __forceinline__ void fma2(ull& d, ull a, ull b) {
    asm("fma.rn.f32x2 %0, %1, %2, %0;" : "+l"(d) : "l"(a), "l"(b));
}
__device__ __forceinline__ ull mul2(ull a, ull b) {
    ull d; asm("mul.rn.f32x2 %0, %1, %2;" : "=l"(d) : "l"(a), "l"(b)); return d;
}
__device__ __forceinline__ ull add2(ull a, ull b) {
    ull d; asm("add.rn.f32x2 %0, %1, %2;" : "=l"(d) : "l"(a), "l"(b)); return d;
}
__device__ __forceinline__ float2 unpk2(ull v) {
    float2 r; asm("mov.b64 {%0, %1}, %2;" : "=f"(r.x), "=f"(r.y) : "l"(v)); return r;
}
__device__ __forceinline__ float ex2fast(float x) {
    float y; asm("ex2.approx.f32 %0, %1;" : "=f"(y) : "f"(x)); return y;
}
__device__ __forceinline__ __half2 tanh2fast(__half2 x) {
    __half2 y;
    asm("tanh.approx.f16x2 %0, %1;" : "=r"(*(u32*)&y) : "r"(*(const u32*)&x));
    return y;
}

// ---- fused prep: coeffs + points + rays + opacity mean, one launch ----
#define PREP_BLOCKS ((NP * 24 + 255) / 256)   // 938
__global__ void prep_all(const float* __restrict__ rays_o,
                         const float* __restrict__ rays_d,
                         const float* __restrict__ positions,
                         const int*   __restrict__ sidx,
                         const float* __restrict__ log_delta,
                         const float* __restrict__ log_sigma,
                         const float* __restrict__ raw_op,
                         const float* __restrict__ shc) {
    __shared__ float red[256];
    int b = blockIdx.x, t = threadIdx.x;
    int gid = b * 256 + t;

    if (gid < NP * 24) {   // fp16 channel-planar half-coefficients
        int pt = gid / 24, w = gid % 24;
        int c = w >> 3, g = w & 7;
        const float* base = shc + (size_t)pt * 48;
        __half2 h = __floats2half2_rn(0.5f * base[(2*g)*3 + c], 0.5f * base[(2*g+1)*3 + c]);
        g_cf[gid] = *(const u32*)&h;
    }
    if (gid < NP) {        // point params
        int s = sidx[gid];
        float delta = __expf(log_delta[s]);
        float sigma = __expf(log_sigma[s]);
        float op    = fsigmoid(raw_op[gid]);
        g_pt[gid] = make_float4(positions[gid*3+0], positions[gid*3+1], positions[gid*3+2],
                                -delta * 1.4426950408889634f);
        g_sf[gid] = sigma * op;
    }
    if (gid < NR) {        // ray params + SH basis
        float ox = rays_o[gid*3+0], oy = rays_o[gid*3+1], oz = rays_o[gid*3+2];
        float dx = rays_d[gid*3+0], dy = rays_d[gid*3+1], dz = rays_d[gid*3+2];
        float inv = rsqrtf(dx*dx + dy*dy + dz*dz);
        float x = dx * inv, y = dy * inv, z = dz * inv;
        g_ro[gid] = make_float4(ox, oy, oz, 0.0f);
        g_dn[gid] = make_float4(x, y, z, 0.0f);
        float sh[16];
        sh[0]  = 0.282095f;
        sh[1]  = 0.488603f * y;
        sh[2]  = 0.488603f * z;
        sh[3]  = 0.488603f * x;
        sh[4]  = 1.092548f * x * y;
        sh[5]  = 1.092548f * y * z;
        sh[6]  = 0.315392f * (3.0f * z * z - 1.0f);
        sh[7]  = 1.092548f * x * z;
        sh[8]  = 0.546274f * (x * x - y * y);
        sh[9]  = 0.590044f * y * (3.0f * x * x - y * y);
        sh[10] = 2.890611f * x * y * z;
        sh[11] = 0.457046f * y * (5.0f * z * z - 1.0f);
        sh[12] = 0.373176f * z * (5.0f * z * z - 3.0f);
        sh[13] = 0.457046f * x * (5.0f * z * z - 1.0f);
        sh[14] = 1.445306f * z * (x * x - y * y);
        sh[15] = 0.590044f * x * (x * x - 3.0f * y * y);
#pragma unroll
        for (int k = 0; k < 16; k++) g_shh[gid*16 + k] = __float2half(sh[k]);
    }
    if (b == PREP_BLOCKS - 1) {   // opacity mean (single block reduction)
        float s = 0.0f;
        for (int i = t; i < NP; i += 256) s += fsigmoid(raw_op[i]);
        red[t] = s;
        __syncthreads();
        for (int o = 128; o > 0; o >>= 1) {
            if (t < o) red[t] += red[t + o];
            __syncthreads();
        }
        if (t == 0) g_opmean = red[0] * (1.0f / (float)NP);
    }
}

// 128 threads, TWO rays/thread (r0 = blk*256+tid, r1 = r0+128).
// One static 125-point tile per CTA: single smem fill, single sync pair.
// SH logits: fp16 HFMA2 (lanes = rayA, rayB); geometry packed f32x2;
// sigmoid tanh.approx.f16x2 (coeffs pre-scaled by 0.5); gaussian ex2.approx.
__global__ void __launch_bounds__(128, 5)
main_k() {
    int tid   = threadIdx.x;
    int r0    = blockIdx.x * 256 + tid;
    int r1    = r0 + 128;
    int chunk = blockIdx.y;

    float4 oA = g_ro[r0], oB = g_ro[r1];
    float4 dA = g_dn[r0], dB = g_dn[r1];
    ull nox = pk2(-oA.x, -oB.x), noy = pk2(-oA.y, -oB.y), noz = pk2(-oA.z, -oB.z);
    ull ddx = pk2(dA.x, dB.x),  ddy = pk2(dA.y, dB.y),  ddz = pk2(dA.z, dB.z);

    __half2 sh[16];
#pragma unroll
    for (int k = 0; k < 16; k++)
        sh[k] = __halves2half2(g_shh[r0*16 + k], g_shh[r1*16 + k]);

    float SA = 0, arA = 0, agA = 0, abA = 0, adA = 0;
    float SB = 0, arB = 0, agB = 0, abB = 0, adB = 0;

    // order by alignment: 16B-aligned arrays first
    __shared__ __align__(16) u32    s_cf[TILE * 24];   // read as uint4
    __shared__ __align__(16) float4 s_pt[TILE];
    __shared__ float  s_sf[TILE];

    const __half2 half05 = __floats2half2_rn(0.5f, 0.5f);

    int p0 = chunk * PPC;
    for (int i = tid; i < TILE; i += 128) {
        s_pt[i] = g_pt[p0 + i];
        s_sf[i] = g_sf[p0 + i];
    }
    {
        const uint4* src = (const uint4*)(g_cf + (size_t)p0 * 24);
        uint4* dst = (uint4*)s_cf;
        for (int i = tid; i < TILE * 6; i += 128) dst[i] = src[i];
    }
    __syncthreads();

#pragma unroll 2
    for (int j = 0; j < TILE; j++) {
        float4 p = s_pt[j];
        float sf = s_sf[j];

        // packed geometry (rayA, rayB)
        ull px = pk2(p.x, p.x), py = pk2(p.y, p.y), pz = pk2(p.z, p.z);
        ull rx = add2(px, nox), ry = add2(py, noy), rz = add2(pz, noz);
        ull d2p = mul2(rx, rx); fma2(d2p, ry, ry); fma2(d2p, rz, rz);
        ull dtp = mul2(rx, ddx); fma2(dtp, ry, ddy); fma2(dtp, rz, ddz);
        float2 d2 = unpk2(d2p), dt = unpk2(dtp);

        float riA = rsqrtf(d2.x);
        float distA = d2.x * riA;
        float tA  = fmaf(-dt.x, riA, 1.0f);
        float wA  = ex2fast(p.w * (tA * tA)) * sf * riA;

        float riB = rsqrtf(d2.y);
        float distB = d2.y * riB;
        float tB  = fmaf(-dt.y, riB, 1.0f);
        float wB  = ex2fast(p.w * (tB * tB)) * sf * riB;

        // fp16 SH half-logits, lanes = (A,B); even/odd chains per channel
        const uint4* cf = (const uint4*)&s_cf[j * 24];
        uint4 q0 = cf[0], q1 = cf[1];
        uint4 q2 = cf[2], q3 = cf[3];
        uint4 q4 = cf[4], q5 = cf[5];

        __half2 e0 = __floats2half2_rn(0.f,0.f), o0 = e0;
        __half2 e1 = e0, o1 = e0, e2 = e0, o2 = e0;
#define CH(acc_e, acc_o, qa, qb)                                          \
        {                                                                  \
            __half2 c;                                                     \
            c = *(const __half2*)&qa.x;                                    \
            acc_e = __hfma2(__low2half2(c),  sh[0], acc_e);                \
            acc_o = __hfma2(__high2half2(c), sh[1], acc_o);                \
            c = *(const __half2*)&qa.y;                                    \
            acc_e = __hfma2(__low2half2(c),  sh[2], acc_e);                \
            acc_o = __hfma2(__high2half2(c), sh[3], acc_o);                \
            c = *(const __half2*)&qa.z;                                    \
            acc_e = __hfma2(__low2half2(c),  sh[4], acc_e);                \
            acc_o = __hfma2(__high2half2(c), sh[5], acc_o);                \
            c = *(const __half2*)&qa.w;                                    \
            acc_e = __hfma2(__low2half2(c),  sh[6], acc_e);                \
            acc_o = __hfma2(__high2half2(c), sh[7], acc_o);                \
            c = *(const __half2*)&qb.x;                                    \
            acc_e = __hfma2(__low2half2(c),  sh[8], acc_e);                \
            acc_o = __hfma2(__high2half2(c), sh[9], acc_o);                \
            c = *(const __half2*)&qb.y;                                    \
            acc_e = __hfma2(__low2half2(c),  sh[10], acc_e);               \
            acc_o = __hfma2(__high2half2(c), sh[11], acc_o);               \
            c = *(const __half2*)&qb.z;                                    \
            acc_e = __hfma2(__low2half2(c),  sh[12], acc_e);               \
            acc_o = __hfma2(__high2half2(c), sh[13], acc_o);               \
            c = *(const __half2*)&qb.w;                                    \
            acc_e = __hfma2(__low2half2(c),  sh[14], acc_e);               \
            acc_o = __hfma2(__high2half2(c), sh[15], acc_o);               \
        }
        CH(e0, o0, q0, q1)
        CH(e1, o1, q2, q3)
        CH(e2, o2, q4, q5)
#undef CH
        __half2 col0 = __hfma2(half05, tanh2fast(__hadd2(e0, o0)), half05);
        __half2 col1 = __hfma2(half05, tanh2fast(__hadd2(e1, o1)), half05);
        __half2 col2 = __hfma2(half05, tanh2fast(__hadd2(e2, o2)), half05);

        SA += wA; adA = fmaf(wA, distA, adA);
        arA = fmaf(wA, __low2float(col0), arA);
        agA = fmaf(wA, __low2float(col1), agA);
        abA = fmaf(wA, __low2float(col2), abA);
        SB += wB; adB = fmaf(wB, distB, adB);
        arB = fmaf(wB, __high2float(col0), arB);
        agB = fmaf(wB, __high2float(col1), agB);
        abB = fmaf(wB, __high2float(col2), abB);
    }

    int iA = chunk * NR + r0;
    g_part[0 * NCHUNK * NR + iA] = SA;
    g_part[1 * NCHUNK * NR + iA] = arA;
    g_part[2 * NCHUNK * NR + iA] = agA;
    g_part[3 * NCHUNK * NR + iA] = abA;
    g_part[4 * NCHUNK * NR + iA] = adA;
    int iB = chunk * NR + r1;
    g_part[0 * NCHUNK * NR + iB] = SB;
    g_part[1 * NCHUNK * NR + iB] = arB;
    g_part[2 * NCHUNK * NR + iB] = agB;
    g_part[3 * NCHUNK * NR + iB] = abB;
    g_part[4 * NCHUNK * NR + iB] = adB;
}

__global__ void finalize(float* __restrict__ out) {
    int ray = blockIdx.x * 256 + threadIdx.x;
    if (ray >= NR) return;
    float S = 0, ar = 0, ag = 0, ab = 0, ad = 0;
    for (int c = 0; c < NCHUNK; c++) {
        int idx = c * NR + ray;
        S  += g_part[0 * NCHUNK * NR + idx];
        ar += g_part[1 * NCHUNK * NR + idx];
        ag += g_part[2 * NCHUNK * NR + idx];
        ab += g_part[3 * NCHUNK * NR + idx];
        ad += g_part[4 * NCHUNK * NR + idx];
    }
    float inv = __fdividef(1.0f, S + 1e-8f);
    out[ray*3 + 0] = ar * inv;
    out[ray*3 + 1] = ag * inv;
    out[ray*3 + 2] = ab * inv;
    out[3*NR + ray] = ad * inv;   // depth
    out[4*NR + ray] = g_opmean;   // opac (broadcast mean opacity)
}

extern "C" void kernel_launch(void* const* d_in, const int* in_sizes, int n_in,
                              void* d_out, int out_size) {
    const float* rays_o    = (const float*)d_in[0];
    const float* rays_d    = (const float*)d_in[1];
    const float* positions = (const float*)d_in[2];
    const int*   sidx      = (const int*)  d_in[3];
    const float* log_delta = (const float*)d_in[4];
    const float* log_sigma = (const float*)d_in[5];
    const float* raw_op    = (const float*)d_in[6];
    const float* shc       = (const float*)d_in[7];
    float* out = (float*)d_out;

    prep_all<<<PREP_BLOCKS, 256>>>(rays_o, rays_d, positions, sidx,
                                   log_delta, log_sigma, raw_op, shc);
    main_k<<<dim3(NR / 256, NCHUNK), 128>>>();
    finalize<<<NR / 256, 256>>>(out);
}

// round 14
// speedup vs baseline: 2.1043x; 1.0457x over previous
#include <cuda_runtime.h>
#include <cuda_fp16.h>

#define NP 10000
#define NR 4096
#define NCHUNK 80
#define PPC 125       // points per chunk == TILE (one smem fill per CTA)
#define TILE 125

typedef unsigned long long ull;
typedef unsigned int u32;

// ---- static scratch (no allocations allowed) ----
__device__ ull    g_pp[NP * 6];      // per point: (x,x),(y,y),(z,z),(pw,pw),(lsf,lsf),pad
__device__ u32    g_cf[NP * 24];     // [pt][c*8+g] = half2(0.5*cf[2g][c], 0.5*cf[2g+1][c])
__device__ float4 g_ro[NR];
__device__ float4 g_dn[NR];
__device__ __half g_shh[NR * 16];    // fp16 SH basis per ray
__device__ float  g_part[5 * NCHUNK * NR];
__device__ float  g_opmean;

__device__ __forceinline__ float fsigmoid(float x) { return __fdividef(1.0f, 1.0f + __expf(-x)); }

// ---- packed f32x2 helpers (sm_103a) ----
__device__ __forceinline__ ull pk2(float a, float b) {
    ull r; asm("mov.b64 %0, {%1, %2};" : "=l"(r) : "f"(a), "f"(b)); return r;
}
__device__ __forceinline__ void fma2(ull& d, ull a, ull b) {
    asm("fma.rn.f32x2 %0, %1, %2, %0;" : "+l"(d) : "l"(a), "l"(b));
}
__device__ __forceinline__ ull fma2n(ull a, ull b, ull c) {
    ull d; asm("fma.rn.f32x2 %0, %1, %2, %3;" : "=l"(d) : "l"(a), "l"(b), "l"(c)); return d;
}
__device__ __forceinline__ ull mul2(ull a, ull b) {
    ull d; asm("mul.rn.f32x2 %0, %1, %2;" : "=l"(d) : "l"(a), "l"(b)); return d;
}
__device__ __forceinline__ ull add2(ull a, ull b) {
    ull d; asm("add.rn.f32x2 %0, %1, %2;" : "=l"(d) : "l"(a), "l"(b)); return d;
}
__device__ __forceinline__ float2 unpk2(ull v) {
    float2 r; asm("mov.b64 {%0, %1}, %2;" : "=f"(r.x), "=f"(r.y) : "l"(v)); return r;
}
__device__ __forceinline__ float ex2fast(float x) {
    float y; asm("ex2.approx.f32 %0, %1;" : "=f"(y) : "f"(x)); return y;
}
__device__ __forceinline__ __half2 tanh2fast(__half2 x) {
    __half2 y;
    asm("tanh.approx.f16x2 %0, %1;" : "=r"(*(u32*)&y) : "r"(*(const u32*)&x));
    return y;
}

// ---- fused prep: coeffs + points + rays + opacity mean, one launch ----
#define PREP_BLOCKS ((NP * 24 + 255) / 256)   // 938
__global__ void prep_all(const float* __restrict__ rays_o,
                         const float* __restrict__ rays_d,
                         const float* __restrict__ positions,
                         const int*   __restrict__ sidx,
                         const float* __restrict__ log_delta,
                         const float* __restrict__ log_sigma,
                         const float* __restrict__ raw_op,
                         const float* __restrict__ shc) {
    __shared__ float red[256];
    int b = blockIdx.x, t = threadIdx.x;
    int gid = b * 256 + t;

    if (gid < NP * 24) {   // fp16 channel-planar half-coefficients
        int pt = gid / 24, w = gid % 24;
        int c = w >> 3, g = w & 7;
        const float* base = shc + (size_t)pt * 48;
        __half2 h = __floats2half2_rn(0.5f * base[(2*g)*3 + c], 0.5f * base[(2*g+1)*3 + c]);
        g_cf[gid] = *(const u32*)&h;
    }
    if (gid < NP) {        // point params, pre-broadcast f32x2 layout
        int s = sidx[gid];
        float delta = __expf(log_delta[s]);
        float sigma = __expf(log_sigma[s]);
        float op    = fsigmoid(raw_op[gid]);
        float pw    = -delta * 1.4426950408889634f;   // -delta*log2(e)
        float lsf   = __log2f(sigma * op);            // fold sigma*op into exponent
        float x = positions[gid*3+0], y = positions[gid*3+1], z = positions[gid*3+2];
        g_pp[gid*6 + 0] = pk2(x, x);
        g_pp[gid*6 + 1] = pk2(y, y);
        g_pp[gid*6 + 2] = pk2(z, z);
        g_pp[gid*6 + 3] = pk2(pw, pw);
        g_pp[gid*6 + 4] = pk2(lsf, lsf);
        g_pp[gid*6 + 5] = 0ULL;
    }
    if (gid < NR) {        // ray params + SH basis
        float ox = rays_o[gid*3+0], oy = rays_o[gid*3+1], oz = rays_o[gid*3+2];
        float dx = rays_d[gid*3+0], dy = rays_d[gid*3+1], dz = rays_d[gid*3+2];
        float inv = rsqrtf(dx*dx + dy*dy + dz*dz);
        float x = dx * inv, y = dy * inv, z = dz * inv;
        g_ro[gid] = make_float4(ox, oy, oz, 0.0f);
        g_dn[gid] = make_float4(x, y, z, 0.0f);
        float sh[16];
        sh[0]  = 0.282095f;
        sh[1]  = 0.488603f * y;
        sh[2]  = 0.488603f * z;
        sh[3]  = 0.488603f * x;
        sh[4]  = 1.092548f * x * y;
        sh[5]  = 1.092548f * y * z;
        sh[6]  = 0.315392f * (3.0f * z * z - 1.0f);
        sh[7]  = 1.092548f * x * z;
        sh[8]  = 0.546274f * (x * x - y * y);
        sh[9]  = 0.590044f * y * (3.0f * x * x - y * y);
        sh[10] = 2.890611f * x * y * z;
        sh[11] = 0.457046f * y * (5.0f * z * z - 1.0f);
        sh[12] = 0.373176f * z * (5.0f * z * z - 3.0f);
        sh[13] = 0.457046f * x * (5.0f * z * z - 1.0f);
        sh[14] = 1.445306f * z * (x * x - y * y);
        sh[15] = 0.590044f * x * (x * x - 3.0f * y * y);
#pragma unroll
        for (int k = 0; k < 16; k++) g_shh[gid*16 + k] = __float2half(sh[k]);
    }
    if (b == PREP_BLOCKS - 1) {   // opacity mean (single block reduction)
        float s = 0.0f;
        for (int i = t; i < NP; i += 256) s += fsigmoid(raw_op[i]);
        red[t] = s;
        __syncthreads();
        for (int o = 128; o > 0; o >>= 1) {
            if (t < o) red[t] += red[t + o];
            __syncthreads();
        }
        if (t == 0) g_opmean = red[0] * (1.0f / (float)NP);
    }
}

// 128 threads, TWO rays/thread (r0 = blk*256+tid, r1 = r0+128).
// Fully packed f32x2 pipeline in (rayA, rayB) lanes: geometry, weight epilog,
// and accumulators. SH logits: fp16 HFMA2; sigmoid tanh.approx.f16x2.
__global__ void __launch_bounds__(128, 5)
main_k() {
    int tid   = threadIdx.x;
    int r0    = blockIdx.x * 256 + tid;
    int r1    = r0 + 128;
    int chunk = blockIdx.y;

    float4 oA = g_ro[r0], oB = g_ro[r1];
    float4 dA = g_dn[r0], dB = g_dn[r1];
    ull nox = pk2(-oA.x, -oB.x), noy = pk2(-oA.y, -oB.y), noz = pk2(-oA.z, -oB.z);
    ull ndx = pk2(-dA.x, -dB.x), ndy = pk2(-dA.y, -dB.y), ndz = pk2(-dA.z, -dB.z);
    const ull one_p = pk2(1.0f, 1.0f);

    __half2 sh[16];
#pragma unroll
    for (int k = 0; k < 16; k++)
        sh[k] = __halves2half2(g_shh[r0*16 + k], g_shh[r1*16 + k]);

    ull S_p = 0, ad_p = 0, ar_p = 0, ag_p = 0, ab_p = 0;   // +0.0 packed

    // order by alignment: 16B-aligned arrays first
    __shared__ __align__(16) u32 s_cf[TILE * 24];   // read as uint4
    __shared__ __align__(16) ull s_pp[TILE * 6];    // read as ulonglong2

    const __half2 half05 = __floats2half2_rn(0.5f, 0.5f);

    int p0 = chunk * PPC;
    {
        const uint4* srcp = (const uint4*)(g_pp + (size_t)p0 * 6);
        uint4* dstp = (uint4*)s_pp;
        for (int i = tid; i < TILE * 3; i += 128) dstp[i] = srcp[i];
        const uint4* src = (const uint4*)(g_cf + (size_t)p0 * 24);
        uint4* dst = (uint4*)s_cf;
        for (int i = tid; i < TILE * 6; i += 128) dst[i] = src[i];
    }
    __syncthreads();

#pragma unroll 2
    for (int j = 0; j < TILE; j++) {
        const ulonglong2* pp = (const ulonglong2*)&s_pp[j * 6];
        ulonglong2 pa = pp[0], pb = pp[1], pc = pp[2];
        // pa = (x,x),(y,y); pb = (z,z),(pw,pw); pc = (lsf,lsf),pad

        // packed geometry (rayA, rayB lanes)
        ull rx = add2(pa.x, nox), ry = add2(pa.y, noy), rz = add2(pb.x, noz);
        ull d2p = mul2(rx, rx); fma2(d2p, ry, ry); fma2(d2p, rz, rz);
        ull ndt = mul2(rx, ndx); fma2(ndt, ry, ndy); fma2(ndt, rz, ndz); // = -(rel.d)

        float2 d2 = unpk2(d2p);
        ull ri_p = pk2(rsqrtf(d2.x), rsqrtf(d2.y));
        ull dist_p = mul2(d2p, ri_p);
        ull t_p  = fma2n(ndt, ri_p, one_p);        // 1 - dot
        ull t2_p = mul2(t_p, t_p);
        ull arg_p = fma2n(pb.y, t2_p, pc.x);       // pw*t^2 + lsf
        float2 ag2 = unpk2(arg_p);
        ull w_p = mul2(pk2(ex2fast(ag2.x), ex2fast(ag2.y)), ri_p);

        // fp16 SH half-logits, lanes = (A,B); even/odd chains per channel
        const uint4* cf = (const uint4*)&s_cf[j * 24];
        uint4 q0 = cf[0], q1 = cf[1];
        uint4 q2 = cf[2], q3 = cf[3];
        uint4 q4 = cf[4], q5 = cf[5];

        __half2 e0 = __floats2half2_rn(0.f,0.f), o0 = e0;
        __half2 e1 = e0, o1 = e0, e2 = e0, o2 = e0;
#define CH(acc_e, acc_o, qa, qb)                                          \
        {                                                                  \
            __half2 c;                                                     \
            c = *(const __half2*)&qa.x;                                    \
            acc_e = __hfma2(__low2half2(c),  sh[0], acc_e);                \
            acc_o = __hfma2(__high2half2(c), sh[1], acc_o);                \
            c = *(const __half2*)&qa.y;                                    \
            acc_e = __hfma2(__low2half2(c),  sh[2], acc_e);                \
            acc_o = __hfma2(__high2half2(c), sh[3], acc_o);                \
            c = *(const __half2*)&qa.z;                                    \
            acc_e = __hfma2(__low2half2(c),  sh[4], acc_e);                \
            acc_o = __hfma2(__high2half2(c), sh[5], acc_o);                \
            c = *(const __half2*)&qa.w;                                    \
            acc_e = __hfma2(__low2half2(c),  sh[6], acc_e);                \
            acc_o = __hfma2(__high2half2(c), sh[7], acc_o);                \
            c = *(const __half2*)&qb.x;                                    \
            acc_e = __hfma2(__low2half2(c),  sh[8], acc_e);                \
            acc_o = __hfma2(__high2half2(c), sh[9], acc_o);                \
            c = *(const __half2*)&qb.y;                                    \
            acc_e = __hfma2(__low2half2(c),  sh[10], acc_e);               \
            acc_o = __hfma2(__high2half2(c), sh[11], acc_o);               \
            c = *(const __half2*)&qb.z;                                    \
            acc_e = __hfma2(__low2half2(c),  sh[12], acc_e);               \
            acc_o = __hfma2(__high2half2(c), sh[13], acc_o);               \
            c = *(const __half2*)&qb.w;                                    \
            acc_e = __hfma2(__low2half2(c),  sh[14], acc_e);               \
            acc_o = __hfma2(__high2half2(c), sh[15], acc_o);               \
        }
        CH(e0, o0, q0, q1)
        CH(e1, o1, q2, q3)
        CH(e2, o2, q4, q5)
#undef CH
        __half2 col0 = __hfma2(half05, tanh2fast(__hadd2(e0, o0)), half05);
        __half2 col1 = __hfma2(half05, tanh2fast(__hadd2(e1, o1)), half05);
        __half2 col2 = __hfma2(half05, tanh2fast(__hadd2(e2, o2)), half05);

        // packed accumulation (lanes A,B)
        float2 c0f = __half22float2(col0);
        float2 c1f = __half22float2(col1);
        float2 c2f = __half22float2(col2);
        S_p  = add2(S_p, w_p);
        fma2(ad_p, w_p, dist_p);
        fma2(ar_p, w_p, pk2(c0f.x, c0f.y));
        fma2(ag_p, w_p, pk2(c1f.x, c1f.y));
        fma2(ab_p, w_p, pk2(c2f.x, c2f.y));
    }

    float2 Sf = unpk2(S_p), adf = unpk2(ad_p);
    float2 arf = unpk2(ar_p), agf = unpk2(ag_p), abf = unpk2(ab_p);

    int iA = chunk * NR + r0;
    g_part[0 * NCHUNK * NR + iA] = Sf.x;
    g_part[1 * NCHUNK * NR + iA] = arf.x;
    g_part[2 * NCHUNK * NR + iA] = agf.x;
    g_part[3 * NCHUNK * NR + iA] = abf.x;
    g_part[4 * NCHUNK * NR + iA] = adf.x;
    int iB = chunk * NR + r1;
    g_part[0 * NCHUNK * NR + iB] = Sf.y;
    g_part[1 * NCHUNK * NR + iB] = arf.y;
    g_part[2 * NCHUNK * NR + iB] = agf.y;
    g_part[3 * NCHUNK * NR + iB] = abf.y;
    g_part[4 * NCHUNK * NR + iB] = adf.y;
}

__global__ void finalize(float* __restrict__ out) {
    int ray = blockIdx.x * 256 + threadIdx.x;
    if (ray >= NR) return;
    float S = 0, ar = 0, ag = 0, ab = 0, ad = 0;
    for (int c = 0; c < NCHUNK; c++) {
        int idx = c * NR + ray;
        S  += g_part[0 * NCHUNK * NR + idx];
        ar += g_part[1 * NCHUNK * NR + idx];
        ag += g_part[2 * NCHUNK * NR + idx];
        ab += g_part[3 * NCHUNK * NR + idx];
        ad += g_part[4 * NCHUNK * NR + idx];
    }
    float inv = __fdividef(1.0f, S + 1e-8f);
    out[ray*3 + 0] = ar * inv;
    out[ray*3 + 1] = ag * inv;
    out[ray*3 + 2] = ab * inv;
    out[3*NR + ray] = ad * inv;   // depth
    out[4*NR + ray] = g_opmean;   // opac (broadcast mean opacity)
}

extern "C" void kernel_launch(void* const* d_in, const int* in_sizes, int n_in,
                              void* d_out, int out_size) {
    const float* rays_o    = (const float*)d_in[0];
    const float* rays_d    = (const float*)d_in[1];
    const float* positions = (const float*)d_in[2];
    const int*   sidx      = (const int*)  d_in[3];
    const float* log_delta = (const float*)d_in[4];
    const float* log_sigma = (const float*)d_in[5];
    const float* raw_op    = (const float*)d_in[6];
    const float* shc       = (const float*)d_in[7];
    float* out = (float*)d_out;

    prep_all<<<PREP_BLOCKS, 256>>>(rays_o, rays_d, positions, sidx,
                                   log_delta, log_sigma, raw_op, shc);
    main_k<<<dim3(NR / 256, NCHUNK), 128>>>();
    finalize<<<NR / 256, 256>>>(out);
}